// round 3
// baseline (speedup 1.0000x reference)
#include <cuda_runtime.h>
#include <cstdint>

#define BATCH 2
#define SEQ   2048
#define DMODEL 1024
#define NHEAD 16
#define DK    64

// Scratch (allocation-free)
__device__ float g_q[BATCH*NHEAD*SEQ*DK];
__device__ float g_k[BATCH*NHEAD*SEQ*DK];
__device__ float g_v[BATCH*NHEAD*SEQ*DK];
__device__ float g_attn[BATCH*SEQ*DMODEL];
// tf32-pre-rounded inputs
__device__ float g_aq[BATCH*SEQ*DMODEL];
__device__ float g_ak[BATCH*SEQ*DMODEL];
__device__ float g_av[BATCH*SEQ*DMODEL];
__device__ float g_wq[DMODEL*DMODEL];
__device__ float g_wk[DMODEL*DMODEL];
__device__ float g_wv[DMODEL*DMODEL];
__device__ float g_wo[DMODEL*DMODEL];

// ---------- helpers ----------
__device__ __forceinline__ float tfr(float f) {
    unsigned u;
    asm("cvt.rna.tf32.f32 %0, %1;" : "=r"(u) : "f"(f));
    return __uint_as_float(u);
}
__device__ __forceinline__ float4 tf4(float4 v) {
    v.x = tfr(v.x); v.y = tfr(v.y); v.z = tfr(v.z); v.w = tfr(v.w);
    return v;
}
__device__ __forceinline__ void mma_tf32(float c[4],
    unsigned a0, unsigned a1, unsigned a2, unsigned a3,
    unsigned b0, unsigned b1) {
    asm volatile(
        "mma.sync.aligned.m16n8k8.row.col.f32.tf32.tf32.f32 "
        "{%0,%1,%2,%3},{%4,%5,%6,%7},{%8,%9},{%0,%1,%2,%3};"
        : "+f"(c[0]), "+f"(c[1]), "+f"(c[2]), "+f"(c[3])
        : "r"(a0), "r"(a1), "r"(a2), "r"(a3), "r"(b0), "r"(b1));
}
#define CPA16(dst, src) \
    asm volatile("cp.async.cg.shared.global [%0], [%1], 16;" \
                 :: "r"(dst), "l"(src))
#define CPA_COMMIT() asm volatile("cp.async.commit_group;")
#define CPA_WAIT1()  asm volatile("cp.async.wait_group 1;")
#define CPA_WAIT0()  asm volatile("cp.async.wait_group 0;")

// ---------- pre-round pass: tf32(RNA) copies of activations & weights ----------
__global__ __launch_bounds__(256) void round_all(
    const float* __restrict__ q, const float* __restrict__ k,
    const float* __restrict__ v,
    const float* __restrict__ wq, const float* __restrict__ wk,
    const float* __restrict__ wv, const float* __restrict__ wo)
{
    const size_t ACT4 = (size_t)BATCH * SEQ * DMODEL / 4;   // 1048576
    const size_t W4   = (size_t)DMODEL * DMODEL / 4;        // 262144
    size_t idx = (size_t)blockIdx.x * 256 + threadIdx.x;
    const float4* src; float4* dst; size_t n4;
    switch (blockIdx.y) {
        case 0: src = (const float4*)q;  dst = (float4*)g_aq; n4 = ACT4; break;
        case 1: src = (const float4*)k;  dst = (float4*)g_ak; n4 = ACT4; break;
        case 2: src = (const float4*)v;  dst = (float4*)g_av; n4 = ACT4; break;
        case 3: src = (const float4*)wq; dst = (float4*)g_wq; n4 = W4; break;
        case 4: src = (const float4*)wk; dst = (float4*)g_wk; n4 = W4; break;
        case 5: src = (const float4*)wv; dst = (float4*)g_wv; n4 = W4; break;
        default: src = (const float4*)wo; dst = (float4*)g_wo; n4 = W4; break;
    }
    if (idx < n4) dst[idx] = tf4(src[idx]);
}

// ---------- projection GEMM: C = A @ W^T + bias (cp.async double-buffered) ----------
// inputs pre-rounded tf32. qkv=1: z selects {q,k,v}, head-split out (rounded);
// qkv=0: flat out (fp32, final).
#define PST 36
#define PROJ_STAGE (128 * PST * 2)           // floats per stage (As+Ws)
#define PROJ_SMEM_BYTES (2 * PROJ_STAGE * 4) // 73728

__global__ __launch_bounds__(256, 2) void proj_gemm(
    const float* __restrict__ A0, const float* __restrict__ W0,
    const float* __restrict__ B0, float* __restrict__ C0,
    const float* __restrict__ A1, const float* __restrict__ W1,
    const float* __restrict__ B1, float* __restrict__ C1,
    const float* __restrict__ A2, const float* __restrict__ W2,
    const float* __restrict__ B2, float* __restrict__ C2,
    int qkv)
{
    extern __shared__ float smp[];
    const float *A = A0, *W = W0, *bias = B0;
    float* C = C0;
    if (qkv) {
        if (blockIdx.z == 1) { A = A1; W = W1; bias = B1; C = C1; }
        else if (blockIdx.z == 2) { A = A2; W = W2; bias = B2; C = C2; }
    }
    const int tid = threadIdx.x, lane = tid & 31, w = tid >> 5;
    const int g = lane >> 2, t = lane & 3;
    const int wr = w >> 1, wc = w & 1;
    const int mbase = blockIdx.y * 128, nbase = blockIdx.x * 128;
    const int lrow = tid >> 3, lc4 = (tid & 7) * 4;

    float c[2][8][4];
#pragma unroll
    for (int mt = 0; mt < 2; mt++)
#pragma unroll
        for (int nt = 0; nt < 8; nt++)
#pragma unroll
            for (int i = 0; i < 4; i++) c[mt][nt][i] = 0.f;

    auto issue = [&](int k0, int s) {
        float* As = smp + s * PROJ_STAGE;
        float* Ws = As + 128 * PST;
#pragma unroll
        for (int i = 0; i < 4; i++) {
            int row = lrow + i * 32;
            unsigned da = (unsigned)__cvta_generic_to_shared(As + row * PST + lc4);
            CPA16(da, A + (size_t)(mbase + row) * 1024 + k0 + lc4);
            unsigned dw = (unsigned)__cvta_generic_to_shared(Ws + row * PST + lc4);
            CPA16(dw, W + (size_t)(nbase + row) * 1024 + k0 + lc4);
        }
        CPA_COMMIT();
    };
    issue(0, 0);
    issue(32, 1);

    for (int it = 0; it < 32; it++) {
        if (it < 31) { CPA_WAIT1(); } else { CPA_WAIT0(); }
        __syncthreads();
        const float* As = smp + (it & 1) * PROJ_STAGE;
        const float* Ws = As + 128 * PST;
#pragma unroll
        for (int kk = 0; kk < 4; kk++) {
            unsigned a[2][4], b[8][2];
#pragma unroll
            for (int mt = 0; mt < 2; mt++) {
                const float* p = As + (wr * 32 + mt * 16 + g) * PST + kk * 8 + t;
                a[mt][0] = __float_as_uint(p[0]);
                a[mt][1] = __float_as_uint(p[8 * PST]);
                a[mt][2] = __float_as_uint(p[4]);
                a[mt][3] = __float_as_uint(p[8 * PST + 4]);
            }
#pragma unroll
            for (int nt = 0; nt < 8; nt++) {
                const float* p = Ws + (wc * 64 + nt * 8 + g) * PST + kk * 8 + t;
                b[nt][0] = __float_as_uint(p[0]);
                b[nt][1] = __float_as_uint(p[4]);
            }
#pragma unroll
            for (int mt = 0; mt < 2; mt++)
#pragma unroll
                for (int nt = 0; nt < 8; nt++)
                    mma_tf32(c[mt][nt], a[mt][0], a[mt][1], a[mt][2], a[mt][3],
                             b[nt][0], b[nt][1]);
        }
        __syncthreads();
        if (it + 2 < 32) issue((it + 2) * 32, it & 1);
    }
    // epilogue
#pragma unroll
    for (int mt = 0; mt < 2; mt++)
#pragma unroll
        for (int nt = 0; nt < 8; nt++) {
            int rg0 = mbase + wr * 32 + mt * 16 + g;
            int ng0 = nbase + wc * 64 + nt * 8 + 2 * t;
#pragma unroll
            for (int ci = 0; ci < 4; ci++) {
                int mg = rg0 + ((ci >> 1) << 3);
                int ng = ng0 + (ci & 1);
                float v = c[mt][nt][ci] + __ldg(bias + ng);
                if (qkv) {
                    int b_ = mg >> 11, s = mg & 2047, h = ng >> 6, d = ng & 63;
                    C[((size_t)((b_ * NHEAD + h) * SEQ + s)) * DK + d] = tfr(v);
                } else {
                    C[(size_t)mg * DMODEL + ng] = v;
                }
            }
        }
}

// ---------- flash attention (causal, cp.async K/V pipeline) ----------
// grid: (16 q-tiles desc, 32 b*h), 256 threads (8 warps x 16 q-rows)
// smem floats: Qs[128*68] | stage{0,1}: Ks[64*68], Vs[64*72 row-major]
#define AQ_ST 68
#define AV_ST 72
#define AKV_STAGE (64 * AQ_ST + 64 * AV_ST)      // 8960 floats
#define AOFF_S0 (128 * AQ_ST)                    // 8704
#define ATTN_SMEM_BYTES ((AOFF_S0 + 2 * AKV_STAGE) * 4)  // 106496

__global__ __launch_bounds__(256) void attn_kernel()
{
    extern __shared__ float sm[];
    float* Qs = sm;

    const int qt = 15 - blockIdx.x;   // heavy tiles first
    const int bh = blockIdx.y;
    const int qbase = qt * 128;
    const float* qp = g_q + (size_t)bh * SEQ * DK;
    const float* kp = g_k + (size_t)bh * SEQ * DK;
    const float* vp = g_v + (size_t)bh * SEQ * DK;

    const int tid = threadIdx.x, lane = tid & 31, w = tid >> 5;
    const int g = lane >> 2, t = lane & 3;
    const int lrow = tid >> 4, lc4 = (tid & 15) * 4;
    const int nkt = 2 * qt + 2;

    // async Q load (group 0)
#pragma unroll
    for (int i = 0; i < 8; i++) {
        int row = lrow + i * 16;
        unsigned d = (unsigned)__cvta_generic_to_shared(Qs + row * AQ_ST + lc4);
        CPA16(d, qp + (size_t)(qbase + row) * DK + lc4);
    }
    CPA_COMMIT();

    auto issue_kv = [&](int kt, int s) {
        float* Ks = sm + AOFF_S0 + s * AKV_STAGE;
        float* Vs = Ks + 64 * AQ_ST;
        const int kb = kt * 64;
#pragma unroll
        for (int i = 0; i < 4; i++) {
            int row = lrow + i * 16;
            unsigned dk_ = (unsigned)__cvta_generic_to_shared(Ks + row * AQ_ST + lc4);
            CPA16(dk_, kp + (size_t)(kb + row) * DK + lc4);
            unsigned dv = (unsigned)__cvta_generic_to_shared(Vs + row * AV_ST + lc4);
            CPA16(dv, vp + (size_t)(kb + row) * DK + lc4);
        }
        CPA_COMMIT();
    };
    issue_kv(0, 0);
    issue_kv(1, 1);   // nkt >= 2 always

    float m0 = -1e30f, m1 = -1e30f, l0 = 0.f, l1 = 0.f;
    float o[8][4];
#pragma unroll
    for (int nt = 0; nt < 8; nt++)
#pragma unroll
        for (int i = 0; i < 4; i++) o[nt][i] = 0.f;

    for (int kt = 0; kt < nkt; kt++) {
        if (kt + 1 < nkt) { CPA_WAIT1(); } else { CPA_WAIT0(); }
        __syncthreads();
        const float* Ks = sm + AOFF_S0 + (kt & 1) * AKV_STAGE;
        const float* Vs = Ks + 64 * AQ_ST;
        const int kb = kt * 64;

        // ---- S = Q @ K^T ----
        float s[8][4];
#pragma unroll
        for (int nt = 0; nt < 8; nt++)
#pragma unroll
            for (int i = 0; i < 4; i++) s[nt][i] = 0.f;
#pragma unroll
        for (int kk = 0; kk < 8; kk++) {
            const float* ap = Qs + (w * 16 + g) * AQ_ST + kk * 8 + t;
            unsigned a0 = __float_as_uint(ap[0]);
            unsigned a1 = __float_as_uint(ap[8 * AQ_ST]);
            unsigned a2 = __float_as_uint(ap[4]);
            unsigned a3 = __float_as_uint(ap[8 * AQ_ST + 4]);
#pragma unroll
            for (int nt = 0; nt < 8; nt++) {
                const float* bp = Ks + (nt * 8 + g) * AQ_ST + kk * 8 + t;
                mma_tf32(s[nt], a0, a1, a2, a3,
                         __float_as_uint(bp[0]), __float_as_uint(bp[4]));
            }
        }

        // ---- scale + causal mask ----
        const bool masked = (kb + 64 > qbase);
        const int r0 = qbase + w * 16 + g, r1 = r0 + 8;
#pragma unroll
        for (int nt = 0; nt < 8; nt++) {
            int cg = kb + nt * 8 + 2 * t;
            s[nt][0] *= 0.125f; s[nt][1] *= 0.125f;
            s[nt][2] *= 0.125f; s[nt][3] *= 0.125f;
            if (masked) {
                if (cg     > r0) s[nt][0] = -1e9f;
                if (cg + 1 > r0) s[nt][1] = -1e9f;
                if (cg     > r1) s[nt][2] = -1e9f;
                if (cg + 1 > r1) s[nt][3] = -1e9f;
            }
        }

        // ---- warp-local online softmax ----
        float mc0 = -1e30f, mc1 = -1e30f;
#pragma unroll
        for (int nt = 0; nt < 8; nt++) {
            mc0 = fmaxf(mc0, fmaxf(s[nt][0], s[nt][1]));
            mc1 = fmaxf(mc1, fmaxf(s[nt][2], s[nt][3]));
        }
        mc0 = fmaxf(mc0, __shfl_xor_sync(0xffffffffu, mc0, 1));
        mc0 = fmaxf(mc0, __shfl_xor_sync(0xffffffffu, mc0, 2));
        mc1 = fmaxf(mc1, __shfl_xor_sync(0xffffffffu, mc1, 1));
        mc1 = fmaxf(mc1, __shfl_xor_sync(0xffffffffu, mc1, 2));
        float mn0 = fmaxf(m0, mc0), mn1 = fmaxf(m1, mc1);
        float al0 = __expf(m0 - mn0), al1 = __expf(m1 - mn1);
        m0 = mn0; m1 = mn1;
        l0 *= al0; l1 *= al1;
        float rs0 = 0.f, rs1 = 0.f;
#pragma unroll
        for (int nt = 0; nt < 8; nt++) {
            float p0 = __expf(s[nt][0] - mn0);
            float p1 = __expf(s[nt][1] - mn0);
            float p2 = __expf(s[nt][2] - mn1);
            float p3 = __expf(s[nt][3] - mn1);
            rs0 += p0 + p1; rs1 += p2 + p3;
            s[nt][0] = tfr(p0); s[nt][1] = tfr(p1);
            s[nt][2] = tfr(p2); s[nt][3] = tfr(p3);
            o[nt][0] *= al0; o[nt][1] *= al0;
            o[nt][2] *= al1; o[nt][3] *= al1;
        }
        rs0 += __shfl_xor_sync(0xffffffffu, rs0, 1);
        rs0 += __shfl_xor_sync(0xffffffffu, rs0, 2);
        rs1 += __shfl_xor_sync(0xffffffffu, rs1, 1);
        rs1 += __shfl_xor_sync(0xffffffffu, rs1, 2);
        l0 += rs0; l1 += rs1;

        // ---- O += P @ V (shuffle relayout; V row-major stride 72) ----
        const int L0 = g * 4 + (t >> 1);
        const int L1 = L0 + 2;
        const bool sel = t & 1;
#pragma unroll
        for (int kk = 0; kk < 8; kk++) {
            float x0 = __shfl_sync(0xffffffffu, s[kk][0], L0);
            float x1 = __shfl_sync(0xffffffffu, s[kk][1], L0);
            float x2 = __shfl_sync(0xffffffffu, s[kk][2], L0);
            float x3 = __shfl_sync(0xffffffffu, s[kk][3], L0);
            float y0 = __shfl_sync(0xffffffffu, s[kk][0], L1);
            float y1 = __shfl_sync(0xffffffffu, s[kk][1], L1);
            float y2 = __shfl_sync(0xffffffffu, s[kk][2], L1);
            float y3 = __shfl_sync(0xffffffffu, s[kk][3], L1);
            unsigned a0 = __float_as_uint(sel ? x1 : x0);
            unsigned a1 = __float_as_uint(sel ? x3 : x2);
            unsigned a2 = __float_as_uint(sel ? y1 : y0);
            unsigned a3 = __float_as_uint(sel ? y3 : y2);
            const float* brow0 = Vs + (kk * 8 + t) * AV_ST;
            const float* brow1 = Vs + (kk * 8 + t + 4) * AV_ST;
#pragma unroll
            for (int nt = 0; nt < 8; nt++) {
                mma_tf32(o[nt], a0, a1, a2, a3,
                         __float_as_uint(brow0[nt * 8 + g]),
                         __float_as_uint(brow1[nt * 8 + g]));
            }
        }
        __syncthreads();
        if (kt + 2 < nkt) issue_kv(kt + 2, kt & 1);
    }

    // ---- epilogue: O/l (tf32-rounded for the O-projection), merge heads ----
    const int b_ = bh >> 4, h = bh & 15;
    const float il0 = 1.f / l0, il1 = 1.f / l1;
    float* outp = g_attn + ((size_t)b_ * SEQ + qbase) * DMODEL + h * DK;
    const int rl0 = w * 16 + g;
#pragma unroll
    for (int nt = 0; nt < 8; nt++) {
        int dl = nt * 8 + 2 * t;
        outp[(size_t)rl0 * DMODEL + dl]           = tfr(o[nt][0] * il0);
        outp[(size_t)rl0 * DMODEL + dl + 1]       = tfr(o[nt][1] * il0);
        outp[(size_t)(rl0 + 8) * DMODEL + dl]     = tfr(o[nt][2] * il1);
        outp[(size_t)(rl0 + 8) * DMODEL + dl + 1] = tfr(o[nt][3] * il1);
    }
}

// ---------- launch ----------
extern "C" void kernel_launch(void* const* d_in, const int* in_sizes, int n_in,
                              void* d_out, int out_size)
{
    const float* q  = (const float*)d_in[0];
    const float* k  = (const float*)d_in[1];
    const float* v  = (const float*)d_in[2];
    const float* wq = (const float*)d_in[4];
    const float* bq = (const float*)d_in[5];
    const float* wk = (const float*)d_in[6];
    const float* bk = (const float*)d_in[7];
    const float* wv = (const float*)d_in[8];
    const float* bv = (const float*)d_in[9];
    const float* wo = (const float*)d_in[10];
    const float* bo = (const float*)d_in[11];

    float *pq, *pk, *pv, *pa, *paq, *pak, *pav, *pwq, *pwk, *pwv, *pwo;
    cudaGetSymbolAddress((void**)&pq,  g_q);
    cudaGetSymbolAddress((void**)&pk,  g_k);
    cudaGetSymbolAddress((void**)&pv,  g_v);
    cudaGetSymbolAddress((void**)&pa,  g_attn);
    cudaGetSymbolAddress((void**)&paq, g_aq);
    cudaGetSymbolAddress((void**)&pak, g_ak);
    cudaGetSymbolAddress((void**)&pav, g_av);
    cudaGetSymbolAddress((void**)&pwq, g_wq);
    cudaGetSymbolAddress((void**)&pwk, g_wk);
    cudaGetSymbolAddress((void**)&pwv, g_wv);
    cudaGetSymbolAddress((void**)&pwo, g_wo);

    round_all<<<dim3(4096, 7), 256>>>(q, k, v, wq, wk, wv, wo);

    cudaFuncSetAttribute(proj_gemm,
                         cudaFuncAttributeMaxDynamicSharedMemorySize,
                         PROJ_SMEM_BYTES);
    proj_gemm<<<dim3(8, 32, 3), 256, PROJ_SMEM_BYTES>>>(
        paq, pwq, bq, pq,
        pak, pwk, bk, pk,
        pav, pwv, bv, pv, 1);

    cudaFuncSetAttribute(attn_kernel,
                         cudaFuncAttributeMaxDynamicSharedMemorySize,
                         ATTN_SMEM_BYTES);
    attn_kernel<<<dim3(16, 32), 256, ATTN_SMEM_BYTES>>>();

    proj_gemm<<<dim3(8, 32, 1), 256, PROJ_SMEM_BYTES>>>(
        pa, pwo, bo, (float*)d_out,
        nullptr, nullptr, nullptr, nullptr,
        nullptr, nullptr, nullptr, nullptr, 0);
}

// round 6
// speedup vs baseline: 1.0446x; 1.0446x over previous
#include <cuda_runtime.h>
#include <cstdint>

#define BATCH 2
#define SEQ   2048
#define DMODEL 1024
#define NHEAD 16
#define DK    64

// Scratch (allocation-free)
__device__ float g_q[BATCH*NHEAD*SEQ*DK];
__device__ float g_k[BATCH*NHEAD*SEQ*DK];
__device__ float g_v[BATCH*NHEAD*SEQ*DK];
__device__ float g_attn[BATCH*SEQ*DMODEL];

// ---------- helpers ----------
__device__ __forceinline__ float tfr(float f) {
    unsigned u;
    asm("cvt.rna.tf32.f32 %0, %1;" : "=r"(u) : "f"(f));
    return __uint_as_float(u);
}
__device__ __forceinline__ float4 tf4(float4 v) {
    v.x = tfr(v.x); v.y = tfr(v.y); v.z = tfr(v.z); v.w = tfr(v.w);
    return v;
}
__device__ __forceinline__ void mma_tf32(float c[4],
    unsigned a0, unsigned a1, unsigned a2, unsigned a3,
    unsigned b0, unsigned b1) {
    asm volatile(
        "mma.sync.aligned.m16n8k8.row.col.f32.tf32.tf32.f32 "
        "{%0,%1,%2,%3},{%4,%5,%6,%7},{%8,%9},{%0,%1,%2,%3};"
        : "+f"(c[0]), "+f"(c[1]), "+f"(c[2]), "+f"(c[3])
        : "r"(a0), "r"(a1), "r"(a2), "r"(a3), "r"(b0), "r"(b1));
}

// ---------- projection GEMM: C = A @ W^T + bias ----------
// CTA tile 128(M) x 64(N), K-chunk 32, register-prefetch pipeline, 2 CTAs/SM.
// qkv=1: blockIdx.z selects {q,k,v}, writes head-split [b,h,s,d]
// qkv=0: flat [m,n] out
#define PST 36
__global__ __launch_bounds__(256, 2) void proj_gemm(
    const float* __restrict__ A0, const float* __restrict__ W0,
    const float* __restrict__ B0, float* __restrict__ C0,
    const float* __restrict__ A1, const float* __restrict__ W1,
    const float* __restrict__ B1, float* __restrict__ C1,
    const float* __restrict__ A2, const float* __restrict__ W2,
    const float* __restrict__ B2, float* __restrict__ C2,
    int qkv)
{
    __shared__ float As[128 * PST];
    __shared__ float Ws[64 * PST];
    const float *A = A0, *W = W0, *bias = B0;
    float* C = C0;
    if (qkv) {
        if (blockIdx.z == 1) { A = A1; W = W1; bias = B1; C = C1; }
        else if (blockIdx.z == 2) { A = A2; W = W2; bias = B2; C = C2; }
    }
    const int tid = threadIdx.x, lane = tid & 31, w = tid >> 5;
    const int g = lane >> 2, t = lane & 3;
    const int wr = w >> 1, wc = w & 1;
    const int mbase = blockIdx.y * 128, nbase = blockIdx.x * 64;

    const int arow = tid >> 1, acol = (tid & 1) * 16;   // + i*4, i<4
    const int wrow = tid >> 2, wcol = (tid & 3) * 8;    // + i*4, i<2

    float c[2][4][4];
#pragma unroll
    for (int mt = 0; mt < 2; mt++)
#pragma unroll
        for (int nt = 0; nt < 4; nt++)
#pragma unroll
            for (int i = 0; i < 4; i++) c[mt][nt][i] = 0.f;

    float4 ra[4], rw[2];
    const float* Ap = A + (size_t)(mbase + arow) * 1024 + acol;
    const float* Wp = W + (size_t)(nbase + wrow) * 1024 + wcol;
#pragma unroll
    for (int i = 0; i < 4; i++) ra[i] = *(const float4*)(Ap + i * 4);
#pragma unroll
    for (int i = 0; i < 2; i++) rw[i] = *(const float4*)(Wp + i * 4);

    for (int k0 = 0; k0 < 1024; k0 += 32) {
        // store current tile (tf32-rounded)
#pragma unroll
        for (int i = 0; i < 4; i++)
            *(float4*)(As + arow * PST + acol + i * 4) = tf4(ra[i]);
#pragma unroll
        for (int i = 0; i < 2; i++)
            *(float4*)(Ws + wrow * PST + wcol + i * 4) = tf4(rw[i]);
        __syncthreads();
        // prefetch next tile
        if (k0 + 32 < 1024) {
#pragma unroll
            for (int i = 0; i < 4; i++)
                ra[i] = *(const float4*)(Ap + k0 + 32 + i * 4);
#pragma unroll
            for (int i = 0; i < 2; i++)
                rw[i] = *(const float4*)(Wp + k0 + 32 + i * 4);
        }
#pragma unroll
        for (int kk = 0; kk < 4; kk++) {
            unsigned a[2][4], b[4][2];
#pragma unroll
            for (int mt = 0; mt < 2; mt++) {
                const float* p = As + (wr * 32 + mt * 16 + g) * PST + kk * 8 + t;
                a[mt][0] = __float_as_uint(p[0]);
                a[mt][1] = __float_as_uint(p[8 * PST]);
                a[mt][2] = __float_as_uint(p[4]);
                a[mt][3] = __float_as_uint(p[8 * PST + 4]);
            }
#pragma unroll
            for (int nt = 0; nt < 4; nt++) {
                const float* p = Ws + (wc * 32 + nt * 8 + g) * PST + kk * 8 + t;
                b[nt][0] = __float_as_uint(p[0]);
                b[nt][1] = __float_as_uint(p[4]);
            }
#pragma unroll
            for (int mt = 0; mt < 2; mt++)
#pragma unroll
                for (int nt = 0; nt < 4; nt++)
                    mma_tf32(c[mt][nt], a[mt][0], a[mt][1], a[mt][2], a[mt][3],
                             b[nt][0], b[nt][1]);
        }
        __syncthreads();
    }
    // epilogue
#pragma unroll
    for (int mt = 0; mt < 2; mt++)
#pragma unroll
        for (int nt = 0; nt < 4; nt++) {
            int rg0 = mbase + wr * 32 + mt * 16 + g;
            int ng0 = nbase + wc * 32 + nt * 8 + 2 * t;
#pragma unroll
            for (int ci = 0; ci < 4; ci++) {
                int mg = rg0 + ((ci >> 1) << 3);
                int ng = ng0 + (ci & 1);
                float v = c[mt][nt][ci] + __ldg(bias + ng);
                size_t idx;
                if (qkv) {
                    int b_ = mg >> 11, s = mg & 2047, h = ng >> 6, d = ng & 63;
                    idx = ((size_t)((b_ * NHEAD + h) * SEQ + s)) * DK + d;
                } else {
                    idx = (size_t)mg * DMODEL + ng;
                }
                C[idx] = v;
            }
        }
}

// ---------- flash attention (causal, warp-local softmax, shuffle P-relayout) ----------
// grid: (16 q-tiles, 32 b*h), 256 threads (8 warps x 16 q-rows), 2 CTAs/SM
#define AOFF_K 8704
#define AOFF_V 13056
#define ATTN_SMEM_BYTES (17408 * 4)

__global__ __launch_bounds__(256, 2) void attn_kernel()
{
    extern __shared__ float sm[];
    float* Qs = sm;
    float* Ks = sm + AOFF_K;
    float* Vs = sm + AOFF_V;

    const int qt = blockIdx.x;
    const int bh = blockIdx.y;
    const int qbase = qt * 128;
    const float* qp = g_q + (size_t)bh * SEQ * DK;
    const float* kp = g_k + (size_t)bh * SEQ * DK;
    const float* vp = g_v + (size_t)bh * SEQ * DK;

    const int tid = threadIdx.x, lane = tid & 31, w = tid >> 5;
    const int g = lane >> 2, t = lane & 3;

    // ---- load Q tile (tf32) ----
#pragma unroll
    for (int i = 0; i < 8; i++) {
        int f = tid + i * 256;
        int row = f >> 4, c4 = (f & 15) * 4;
        float4 v = *(const float4*)(qp + (size_t)(qbase + row) * DK + c4);
        *(float4*)(Qs + row * 68 + c4) = tf4(v);
    }

    float m0 = -1e30f, m1 = -1e30f, l0 = 0.f, l1 = 0.f;
    float o[8][4];
#pragma unroll
    for (int nt = 0; nt < 8; nt++)
#pragma unroll
        for (int i = 0; i < 4; i++) o[nt][i] = 0.f;

    const int nkt = 2 * qt + 2;
    const int lrow = tid >> 4, lc4 = (tid & 15) * 4;

    // prefetch tile 0
    float4 kr[4], vr4[4];
#pragma unroll
    for (int i = 0; i < 4; i++) {
        kr[i]  = *(const float4*)(kp + (size_t)(lrow + i * 16) * DK + lc4);
        vr4[i] = *(const float4*)(vp + (size_t)(lrow + i * 16) * DK + lc4);
    }
    __syncthreads();

    for (int kt = 0; kt < nkt; kt++) {
        const int kb = kt * 64;
        // ---- store K (row-major) / V (transposed) tiles ----
#pragma unroll
        for (int i = 0; i < 4; i++) {
            int row = lrow + i * 16;
            *(float4*)(Ks + row * 68 + lc4) = tf4(kr[i]);
            Vs[(lc4 + 0) * 68 + row] = tfr(vr4[i].x);
            Vs[(lc4 + 1) * 68 + row] = tfr(vr4[i].y);
            Vs[(lc4 + 2) * 68 + row] = tfr(vr4[i].z);
            Vs[(lc4 + 3) * 68 + row] = tfr(vr4[i].w);
        }
        __syncthreads();
        // prefetch next tile
        if (kt + 1 < nkt) {
            const float* kpn = kp + (size_t)(kb + 64) * DK;
            const float* vpn = vp + (size_t)(kb + 64) * DK;
#pragma unroll
            for (int i = 0; i < 4; i++) {
                kr[i]  = *(const float4*)(kpn + (size_t)(lrow + i * 16) * DK + lc4);
                vr4[i] = *(const float4*)(vpn + (size_t)(lrow + i * 16) * DK + lc4);
            }
        }

        // ---- S = Q @ K^T ----
        float s[8][4];
#pragma unroll
        for (int nt = 0; nt < 8; nt++)
#pragma unroll
            for (int i = 0; i < 4; i++) s[nt][i] = 0.f;
#pragma unroll
        for (int kk = 0; kk < 8; kk++) {
            const float* ap = Qs + (w * 16 + g) * 68 + kk * 8 + t;
            unsigned a0 = __float_as_uint(ap[0]);
            unsigned a1 = __float_as_uint(ap[8 * 68]);
            unsigned a2 = __float_as_uint(ap[4]);
            unsigned a3 = __float_as_uint(ap[8 * 68 + 4]);
#pragma unroll
            for (int nt = 0; nt < 8; nt++) {
                const float* bp = Ks + (nt * 8 + g) * 68 + kk * 8 + t;
                mma_tf32(s[nt], a0, a1, a2, a3,
                         __float_as_uint(bp[0]), __float_as_uint(bp[4]));
            }
        }

        // ---- scale + causal mask ----
        const bool masked = (kb + 64 > qbase);
        const int r0 = qbase + w * 16 + g, r1 = r0 + 8;
#pragma unroll
        for (int nt = 0; nt < 8; nt++) {
            int cg = kb + nt * 8 + 2 * t;
            s[nt][0] *= 0.125f; s[nt][1] *= 0.125f;
            s[nt][2] *= 0.125f; s[nt][3] *= 0.125f;
            if (masked) {
                if (cg     > r0) s[nt][0] = -1e9f;
                if (cg + 1 > r0) s[nt][1] = -1e9f;
                if (cg     > r1) s[nt][2] = -1e9f;
                if (cg + 1 > r1) s[nt][3] = -1e9f;
            }
        }

        // ---- warp-local online softmax ----
        float mc0 = -1e30f, mc1 = -1e30f;
#pragma unroll
        for (int nt = 0; nt < 8; nt++) {
            mc0 = fmaxf(mc0, fmaxf(s[nt][0], s[nt][1]));
            mc1 = fmaxf(mc1, fmaxf(s[nt][2], s[nt][3]));
        }
        mc0 = fmaxf(mc0, __shfl_xor_sync(0xffffffffu, mc0, 1));
        mc0 = fmaxf(mc0, __shfl_xor_sync(0xffffffffu, mc0, 2));
        mc1 = fmaxf(mc1, __shfl_xor_sync(0xffffffffu, mc1, 1));
        mc1 = fmaxf(mc1, __shfl_xor_sync(0xffffffffu, mc1, 2));
        float mn0 = fmaxf(m0, mc0), mn1 = fmaxf(m1, mc1);
        float al0 = __expf(m0 - mn0), al1 = __expf(m1 - mn1);
        m0 = mn0; m1 = mn1;
        l0 *= al0; l1 *= al1;
        float rs0 = 0.f, rs1 = 0.f;
#pragma unroll
        for (int nt = 0; nt < 8; nt++) {
            float p0 = __expf(s[nt][0] - mn0);
            float p1 = __expf(s[nt][1] - mn0);
            float p2 = __expf(s[nt][2] - mn1);
            float p3 = __expf(s[nt][3] - mn1);
            rs0 += p0 + p1; rs1 += p2 + p3;
            s[nt][0] = tfr(p0); s[nt][1] = tfr(p1);
            s[nt][2] = tfr(p2); s[nt][3] = tfr(p3);
            o[nt][0] *= al0; o[nt][1] *= al0;
            o[nt][2] *= al1; o[nt][3] *= al1;
        }
        rs0 += __shfl_xor_sync(0xffffffffu, rs0, 1);
        rs0 += __shfl_xor_sync(0xffffffffu, rs0, 2);
        rs1 += __shfl_xor_sync(0xffffffffu, rs1, 1);
        rs1 += __shfl_xor_sync(0xffffffffu, rs1, 2);
        l0 += rs0; l1 += rs1;

        // ---- O += P @ V (shuffle relayout) ----
        const int L0 = g * 4 + (t >> 1);
        const int L1 = L0 + 2;
        const bool sel = t & 1;
#pragma unroll
        for (int kk = 0; kk < 8; kk++) {
            float x0 = __shfl_sync(0xffffffffu, s[kk][0], L0);
            float x1 = __shfl_sync(0xffffffffu, s[kk][1], L0);
            float x2 = __shfl_sync(0xffffffffu, s[kk][2], L0);
            float x3 = __shfl_sync(0xffffffffu, s[kk][3], L0);
            float y0 = __shfl_sync(0xffffffffu, s[kk][0], L1);
            float y1 = __shfl_sync(0xffffffffu, s[kk][1], L1);
            float y2 = __shfl_sync(0xffffffffu, s[kk][2], L1);
            float y3 = __shfl_sync(0xffffffffu, s[kk][3], L1);
            unsigned a0 = __float_as_uint(sel ? x1 : x0);
            unsigned a1 = __float_as_uint(sel ? x3 : x2);
            unsigned a2 = __float_as_uint(sel ? y1 : y0);
            unsigned a3 = __float_as_uint(sel ? y3 : y2);
#pragma unroll
            for (int nt = 0; nt < 8; nt++) {
                const float* bp = Vs + (nt * 8 + g) * 68 + kk * 8 + t;
                mma_tf32(o[nt], a0, a1, a2, a3,
                         __float_as_uint(bp[0]), __float_as_uint(bp[4]));
            }
        }
        __syncthreads();
    }

    // ---- epilogue ----
    const int b_ = bh >> 4, h = bh & 15;
    const float il0 = 1.f / l0, il1 = 1.f / l1;
    float* outp = g_attn + ((size_t)b_ * SEQ + qbase) * DMODEL + h * DK;
    const int rl0 = w * 16 + g;
#pragma unroll
    for (int nt = 0; nt < 8; nt++) {
        int dl = nt * 8 + 2 * t;
        outp[(size_t)rl0 * DMODEL + dl]           = o[nt][0] * il0;
        outp[(size_t)rl0 * DMODEL + dl + 1]       = o[nt][1] * il0;
        outp[(size_t)(rl0 + 8) * DMODEL + dl]     = o[nt][2] * il1;
        outp[(size_t)(rl0 + 8) * DMODEL + dl + 1] = o[nt][3] * il1;
    }
}

// ---------- launch ----------
extern "C" void kernel_launch(void* const* d_in, const int* in_sizes, int n_in,
                              void* d_out, int out_size)
{
    const float* q  = (const float*)d_in[0];
    const float* k  = (const float*)d_in[1];
    const float* v  = (const float*)d_in[2];
    const float* wq = (const float*)d_in[4];
    const float* bq = (const float*)d_in[5];
    const float* wk = (const float*)d_in[6];
    const float* bk = (const float*)d_in[7];
    const float* wv = (const float*)d_in[8];
    const float* bv = (const float*)d_in[9];
    const float* wo = (const float*)d_in[10];
    const float* bo = (const float*)d_in[11];

    float *pq, *pk, *pv, *pa;
    cudaGetSymbolAddress((void**)&pq, g_q);
    cudaGetSymbolAddress((void**)&pk, g_k);
    cudaGetSymbolAddress((void**)&pv, g_v);
    cudaGetSymbolAddress((void**)&pa, g_attn);

    // fused Q/K/V projections
    proj_gemm<<<dim3(16, 32, 3), 256>>>(q, wq, bq, pq,
                                        k, wk, bk, pk,
                                        v, wv, bv, pv, 1);

    cudaFuncSetAttribute(attn_kernel,
                         cudaFuncAttributeMaxDynamicSharedMemorySize,
                         ATTN_SMEM_BYTES);
    attn_kernel<<<dim3(16, 32), 256, ATTN_SMEM_BYTES>>>();

    proj_gemm<<<dim3(16, 32, 1), 256>>>(pa, wo, bo, (float*)d_out,
                                        nullptr, nullptr, nullptr, nullptr,
                                        nullptr, nullptr, nullptr, nullptr, 0);
}

// round 8
// speedup vs baseline: 1.4956x; 1.4317x over previous
#include <cuda_runtime.h>
#include <cstdint>

#define BATCH 2
#define SEQ   2048
#define DMODEL 1024
#define NHEAD 16
#define DK    64

// Scratch (allocation-free)
__device__ float g_q[BATCH*NHEAD*SEQ*DK];
__device__ float g_k[BATCH*NHEAD*SEQ*DK];
__device__ float g_v[BATCH*NHEAD*SEQ*DK];
__device__ float g_attn[BATCH*SEQ*DMODEL];

// ---------- helpers ----------
__device__ __forceinline__ float tfr(float f) {
    unsigned u;
    asm("cvt.rna.tf32.f32 %0, %1;" : "=r"(u) : "f"(f));
    return __uint_as_float(u);
}
__device__ __forceinline__ float4 tf4(float4 v) {
    v.x = tfr(v.x); v.y = tfr(v.y); v.z = tfr(v.z); v.w = tfr(v.w);
    return v;
}
__device__ __forceinline__ void mma_tf32(float c[4],
    unsigned a0, unsigned a1, unsigned a2, unsigned a3,
    unsigned b0, unsigned b1) {
    asm volatile(
        "mma.sync.aligned.m16n8k8.row.col.f32.tf32.tf32.f32 "
        "{%0,%1,%2,%3},{%4,%5,%6,%7},{%8,%9},{%0,%1,%2,%3};"
        : "+f"(c[0]), "+f"(c[1]), "+f"(c[2]), "+f"(c[3])
        : "r"(a0), "r"(a1), "r"(a2), "r"(a3), "r"(b0), "r"(b1));
}

// ---------- projection GEMM: C = A @ W^T + bias ----------
// 128x128 CTA tile, K-chunk 32, DOUBLE-BUFFERED smem, one sync per chunk.
// qkv=1: blockIdx.z selects {q,k,v}, head-split out; qkv=0: flat out.
#define PST 36
#define PSTAGE (128 * PST * 2)              // floats per stage (As+Ws) = 9216
#define PROJ_SMEM_BYTES (2 * PSTAGE * 4)    // 73728

__global__ __launch_bounds__(256) void proj_gemm(
    const float* __restrict__ A0, const float* __restrict__ W0,
    const float* __restrict__ B0, float* __restrict__ C0,
    const float* __restrict__ A1, const float* __restrict__ W1,
    const float* __restrict__ B1, float* __restrict__ C1,
    const float* __restrict__ A2, const float* __restrict__ W2,
    const float* __restrict__ B2, float* __restrict__ C2,
    int qkv)
{
    extern __shared__ float smp[];
    const float *A = A0, *W = W0, *bias = B0;
    float* C = C0;
    if (qkv) {
        if (blockIdx.z == 1) { A = A1; W = W1; bias = B1; C = C1; }
        else if (blockIdx.z == 2) { A = A2; W = W2; bias = B2; C = C2; }
    }
    const int tid = threadIdx.x, lane = tid & 31, w = tid >> 5;
    const int g = lane >> 2, t = lane & 3;
    const int wr = w >> 1, wc = w & 1;
    const int mbase = blockIdx.y * 128, nbase = blockIdx.x * 128;
    const int lrow = tid >> 3, lc4 = (tid & 7) * 4;    // + i*32 rows

    float c[2][8][4];
#pragma unroll
    for (int mt = 0; mt < 2; mt++)
#pragma unroll
        for (int nt = 0; nt < 8; nt++)
#pragma unroll
            for (int i = 0; i < 4; i++) c[mt][nt][i] = 0.f;

    float4 ra[4], rw[4];
    auto ldg = [&](int kt) {
        const float* Ap = A + (size_t)(mbase + lrow) * 1024 + kt * 32 + lc4;
        const float* Wp = W + (size_t)(nbase + lrow) * 1024 + kt * 32 + lc4;
#pragma unroll
        for (int i = 0; i < 4; i++) {
            ra[i] = *(const float4*)(Ap + (size_t)i * 32 * 1024);
            rw[i] = *(const float4*)(Wp + (size_t)i * 32 * 1024);
        }
    };
    auto sts = [&](int s) {
        float* As = smp + s * PSTAGE;
        float* Ws = As + 128 * PST;
#pragma unroll
        for (int i = 0; i < 4; i++) {
            *(float4*)(As + (lrow + i * 32) * PST + lc4) = tf4(ra[i]);
            *(float4*)(Ws + (lrow + i * 32) * PST + lc4) = tf4(rw[i]);
        }
    };

    ldg(0); sts(0); ldg(1);
    __syncthreads();

    for (int kt = 0; kt < 32; kt++) {
        if (kt + 1 < 32) sts((kt + 1) & 1);
        if (kt + 2 < 32) ldg(kt + 2);
        const float* As = smp + (kt & 1) * PSTAGE;
        const float* Ws = As + 128 * PST;
#pragma unroll
        for (int kk = 0; kk < 4; kk++) {
            unsigned a[2][4], b[8][2];
#pragma unroll
            for (int mt = 0; mt < 2; mt++) {
                const float* p = As + (wr * 32 + mt * 16 + g) * PST + kk * 8 + t;
                a[mt][0] = __float_as_uint(p[0]);
                a[mt][1] = __float_as_uint(p[8 * PST]);
                a[mt][2] = __float_as_uint(p[4]);
                a[mt][3] = __float_as_uint(p[8 * PST + 4]);
            }
#pragma unroll
            for (int nt = 0; nt < 8; nt++) {
                const float* p = Ws + (wc * 64 + nt * 8 + g) * PST + kk * 8 + t;
                b[nt][0] = __float_as_uint(p[0]);
                b[nt][1] = __float_as_uint(p[4]);
            }
#pragma unroll
            for (int mt = 0; mt < 2; mt++)
#pragma unroll
                for (int nt = 0; nt < 8; nt++)
                    mma_tf32(c[mt][nt], a[mt][0], a[mt][1], a[mt][2], a[mt][3],
                             b[nt][0], b[nt][1]);
        }
        __syncthreads();
    }
    // epilogue
#pragma unroll
    for (int mt = 0; mt < 2; mt++)
#pragma unroll
        for (int nt = 0; nt < 8; nt++) {
            int rg0 = mbase + wr * 32 + mt * 16 + g;
            int ng0 = nbase + wc * 64 + nt * 8 + 2 * t;
#pragma unroll
            for (int ci = 0; ci < 4; ci++) {
                int mg = rg0 + ((ci >> 1) << 3);
                int ng = ng0 + (ci & 1);
                float v = c[mt][nt][ci] + __ldg(bias + ng);
                size_t idx;
                if (qkv) {
                    int b_ = mg >> 11, s = mg & 2047, h = ng >> 6, d = ng & 63;
                    idx = ((size_t)((b_ * NHEAD + h) * SEQ + s)) * DK + d;
                } else {
                    idx = (size_t)mg * DMODEL + ng;
                }
                C[idx] = v;
            }
        }
}

// ---------- flash attention ----------
// causal, warp-local softmax, shuffle P-relayout, double-buffered K/V,
// V row-major (conflict-free), one sync per KV tile.
// grid: (16 q-tiles desc, 32 b*h), 256 threads (8 warps x 16 q-rows)
#define AQ_ST 68
#define AV_ST 72
#define AKV_STAGE (64 * AQ_ST + 64 * AV_ST)          // 8960 floats
#define AOFF_S0 (128 * AQ_ST)                        // 8704
#define ATTN_SMEM_BYTES ((AOFF_S0 + 2 * AKV_STAGE) * 4)   // 106496

__global__ __launch_bounds__(256) void attn_kernel()
{
    extern __shared__ float sm[];
    float* Qs = sm;

    const int qt = 15 - blockIdx.x;     // heavy tiles first
    const int bh = blockIdx.y;
    const int qbase = qt * 128;
    const float* qp = g_q + (size_t)bh * SEQ * DK;
    const float* kp = g_k + (size_t)bh * SEQ * DK;
    const float* vp = g_v + (size_t)bh * SEQ * DK;

    const int tid = threadIdx.x, lane = tid & 31, w = tid >> 5;
    const int g = lane >> 2, t = lane & 3;
    const int lrow = tid >> 4, lc4 = (tid & 15) * 4;
    const int nkt = 2 * qt + 2;

    // ---- load Q tile (tf32) ----
#pragma unroll
    for (int i = 0; i < 8; i++) {
        int f = tid + i * 256;
        int row = f >> 4, c4 = (f & 15) * 4;
        float4 v = *(const float4*)(qp + (size_t)(qbase + row) * DK + c4);
        *(float4*)(Qs + row * AQ_ST + c4) = tf4(v);
    }

    float4 kr[4], vr4[4];
    auto ldg_kv = [&](int kt) {
        const float* kpn = kp + (size_t)(kt * 64) * DK;
        const float* vpn = vp + (size_t)(kt * 64) * DK;
#pragma unroll
        for (int i = 0; i < 4; i++) {
            kr[i]  = *(const float4*)(kpn + (size_t)(lrow + i * 16) * DK + lc4);
            vr4[i] = *(const float4*)(vpn + (size_t)(lrow + i * 16) * DK + lc4);
        }
    };
    auto sts_kv = [&](int s) {
        float* Ks = sm + AOFF_S0 + s * AKV_STAGE;
        float* Vs = Ks + 64 * AQ_ST;
#pragma unroll
        for (int i = 0; i < 4; i++) {
            int row = lrow + i * 16;
            *(float4*)(Ks + row * AQ_ST + lc4) = tf4(kr[i]);
            *(float4*)(Vs + row * AV_ST + lc4) = tf4(vr4[i]);
        }
    };

    float m0 = -1e30f, m1 = -1e30f, l0 = 0.f, l1 = 0.f;
    float o[8][4];
#pragma unroll
    for (int nt = 0; nt < 8; nt++)
#pragma unroll
        for (int i = 0; i < 4; i++) o[nt][i] = 0.f;

    ldg_kv(0); sts_kv(0);
    ldg_kv(1);                  // nkt >= 2 always
    __syncthreads();

    for (int kt = 0; kt < nkt; kt++) {
        if (kt + 1 < nkt) sts_kv((kt + 1) & 1);
        if (kt + 2 < nkt) ldg_kv(kt + 2);
        const float* Ks = sm + AOFF_S0 + (kt & 1) * AKV_STAGE;
        const float* Vs = Ks + 64 * AQ_ST;
        const int kb = kt * 64;

        // ---- S = Q @ K^T ----
        float s[8][4];
#pragma unroll
        for (int nt = 0; nt < 8; nt++)
#pragma unroll
            for (int i = 0; i < 4; i++) s[nt][i] = 0.f;
#pragma unroll
        for (int kk = 0; kk < 8; kk++) {
            const float* ap = Qs + (w * 16 + g) * AQ_ST + kk * 8 + t;
            unsigned a0 = __float_as_uint(ap[0]);
            unsigned a1 = __float_as_uint(ap[8 * AQ_ST]);
            unsigned a2 = __float_as_uint(ap[4]);
            unsigned a3 = __float_as_uint(ap[8 * AQ_ST + 4]);
#pragma unroll
            for (int nt = 0; nt < 8; nt++) {
                const float* bp = Ks + (nt * 8 + g) * AQ_ST + kk * 8 + t;
                mma_tf32(s[nt], a0, a1, a2, a3,
                         __float_as_uint(bp[0]), __float_as_uint(bp[4]));
            }
        }

        // ---- scale + causal mask ----
        const bool masked = (kb + 64 > qbase);
        const int r0 = qbase + w * 16 + g, r1 = r0 + 8;
#pragma unroll
        for (int nt = 0; nt < 8; nt++) {
            int cg = kb + nt * 8 + 2 * t;
            s[nt][0] *= 0.125f; s[nt][1] *= 0.125f;
            s[nt][2] *= 0.125f; s[nt][3] *= 0.125f;
            if (masked) {
                if (cg     > r0) s[nt][0] = -1e9f;
                if (cg + 1 > r0) s[nt][1] = -1e9f;
                if (cg     > r1) s[nt][2] = -1e9f;
                if (cg + 1 > r1) s[nt][3] = -1e9f;
            }
        }

        // ---- warp-local online softmax ----
        float mc0 = -1e30f, mc1 = -1e30f;
#pragma unroll
        for (int nt = 0; nt < 8; nt++) {
            mc0 = fmaxf(mc0, fmaxf(s[nt][0], s[nt][1]));
            mc1 = fmaxf(mc1, fmaxf(s[nt][2], s[nt][3]));
        }
        mc0 = fmaxf(mc0, __shfl_xor_sync(0xffffffffu, mc0, 1));
        mc0 = fmaxf(mc0, __shfl_xor_sync(0xffffffffu, mc0, 2));
        mc1 = fmaxf(mc1, __shfl_xor_sync(0xffffffffu, mc1, 1));
        mc1 = fmaxf(mc1, __shfl_xor_sync(0xffffffffu, mc1, 2));
        float mn0 = fmaxf(m0, mc0), mn1 = fmaxf(m1, mc1);
        float al0 = __expf(m0 - mn0), al1 = __expf(m1 - mn1);
        m0 = mn0; m1 = mn1;
        l0 *= al0; l1 *= al1;
        float rs0 = 0.f, rs1 = 0.f;
#pragma unroll
        for (int nt = 0; nt < 8; nt++) {
            float p0 = __expf(s[nt][0] - mn0);
            float p1 = __expf(s[nt][1] - mn0);
            float p2 = __expf(s[nt][2] - mn1);
            float p3 = __expf(s[nt][3] - mn1);
            rs0 += p0 + p1; rs1 += p2 + p3;
            s[nt][0] = tfr(p0); s[nt][1] = tfr(p1);
            s[nt][2] = tfr(p2); s[nt][3] = tfr(p3);
            o[nt][0] *= al0; o[nt][1] *= al0;
            o[nt][2] *= al1; o[nt][3] *= al1;
        }
        rs0 += __shfl_xor_sync(0xffffffffu, rs0, 1);
        rs0 += __shfl_xor_sync(0xffffffffu, rs0, 2);
        rs1 += __shfl_xor_sync(0xffffffffu, rs1, 1);
        rs1 += __shfl_xor_sync(0xffffffffu, rs1, 2);
        l0 += rs0; l1 += rs1;

        // ---- O += P @ V (shuffle relayout; V row-major) ----
        const int L0 = g * 4 + (t >> 1);
        const int L1 = L0 + 2;
        const bool sel = t & 1;
#pragma unroll
        for (int kk = 0; kk < 8; kk++) {
            float x0 = __shfl_sync(0xffffffffu, s[kk][0], L0);
            float x1 = __shfl_sync(0xffffffffu, s[kk][1], L0);
            float x2 = __shfl_sync(0xffffffffu, s[kk][2], L0);
            float x3 = __shfl_sync(0xffffffffu, s[kk][3], L0);
            float y0 = __shfl_sync(0xffffffffu, s[kk][0], L1);
            float y1 = __shfl_sync(0xffffffffu, s[kk][1], L1);
            float y2 = __shfl_sync(0xffffffffu, s[kk][2], L1);
            float y3 = __shfl_sync(0xffffffffu, s[kk][3], L1);
            unsigned a0 = __float_as_uint(sel ? x1 : x0);
            unsigned a1 = __float_as_uint(sel ? x3 : x2);
            unsigned a2 = __float_as_uint(sel ? y1 : y0);
            unsigned a3 = __float_as_uint(sel ? y3 : y2);
            const float* brow0 = Vs + (kk * 8 + t) * AV_ST;
            const float* brow1 = Vs + (kk * 8 + t + 4) * AV_ST;
#pragma unroll
            for (int nt = 0; nt < 8; nt++) {
                mma_tf32(o[nt], a0, a1, a2, a3,
                         __float_as_uint(brow0[nt * 8 + g]),
                         __float_as_uint(brow1[nt * 8 + g]));
            }
        }
        __syncthreads();
    }

    // ---- epilogue: O/l, merge heads -> g_attn [B,S,DMODEL] ----
    const int b_ = bh >> 4, h = bh & 15;
    const float il0 = 1.f / l0, il1 = 1.f / l1;
    float* outp = g_attn + ((size_t)b_ * SEQ + qbase) * DMODEL + h * DK;
    const int rl0 = w * 16 + g;
#pragma unroll
    for (int nt = 0; nt < 8; nt++) {
        int dl = nt * 8 + 2 * t;
        outp[(size_t)rl0 * DMODEL + dl]           = o[nt][0] * il0;
        outp[(size_t)rl0 * DMODEL + dl + 1]       = o[nt][1] * il0;
        outp[(size_t)(rl0 + 8) * DMODEL + dl]     = o[nt][2] * il1;
        outp[(size_t)(rl0 + 8) * DMODEL + dl + 1] = o[nt][3] * il1;
    }
}

// ---------- launch ----------
extern "C" void kernel_launch(void* const* d_in, const int* in_sizes, int n_in,
                              void* d_out, int out_size)
{
    const float* q  = (const float*)d_in[0];
    const float* k  = (const float*)d_in[1];
    const float* v  = (const float*)d_in[2];
    const float* wq = (const float*)d_in[4];
    const float* bq = (const float*)d_in[5];
    const float* wk = (const float*)d_in[6];
    const float* bk = (const float*)d_in[7];
    const float* wv = (const float*)d_in[8];
    const float* bv = (const float*)d_in[9];
    const float* wo = (const float*)d_in[10];
    const float* bo = (const float*)d_in[11];

    float *pq, *pk, *pv, *pa;
    cudaGetSymbolAddress((void**)&pq, g_q);
    cudaGetSymbolAddress((void**)&pk, g_k);
    cudaGetSymbolAddress((void**)&pv, g_v);
    cudaGetSymbolAddress((void**)&pa, g_attn);

    cudaFuncSetAttribute(proj_gemm,
                         cudaFuncAttributeMaxDynamicSharedMemorySize,
                         PROJ_SMEM_BYTES);
    cudaFuncSetAttribute(attn_kernel,
                         cudaFuncAttributeMaxDynamicSharedMemorySize,
                         ATTN_SMEM_BYTES);

    // fused Q/K/V projections
    proj_gemm<<<dim3(8, 32, 3), 256, PROJ_SMEM_BYTES>>>(
        q, wq, bq, pq,
        k, wk, bk, pk,
        v, wv, bv, pv, 1);

    attn_kernel<<<dim3(16, 32), 256, ATTN_SMEM_BYTES>>>();

    proj_gemm<<<dim3(8, 32, 1), 256, PROJ_SMEM_BYTES>>>(
        pa, wo, bo, (float*)d_out,
        nullptr, nullptr, nullptr, nullptr,
        nullptr, nullptr, nullptr, nullptr, 0);
}